// round 2
// baseline (speedup 1.0000x reference)
#include <cuda_runtime.h>
#include <cstdint>
#include <cstddef>

#define TILE_M   128
#define IN_DIM   144
#define HID      64
#define AS       148   // row stride (floats) for A tile and W1T  (conflict-free for frag loads)
#define HS       68    // row stride (floats) for H tile and W2T
#define NTHREADS 256

// SMEM layout (float offsets)
#define oW1 0                        // W1 transposed [n][k], 64 x AS
#define oW2 (oW1 + 64*AS)            // W2 transposed [n][k], 64 x HS
#define oA  (oW2 + 64*HS)            // gathered input tile, 128 x AS
#define oH  (oA + TILE_M*AS)         // hidden tile h1,      128 x HS
#define oP  (oH + TILE_M*HS)         // params: b1,g1,be1,b2,g2,be2,W3 (7x64) + b3
#define SMEM_FLOATS (oP + 452)
#define SMEM_BYTES  (SMEM_FLOATS * 4)

__device__ __forceinline__ float tf32r(float x) {
    unsigned u;
    asm("cvt.rna.tf32.f32 %0, %1;" : "=r"(u) : "f"(x));
    return __uint_as_float(u);
}

__device__ __forceinline__ void mma_tf32(float* c,
                                         unsigned a0, unsigned a1, unsigned a2, unsigned a3,
                                         unsigned b0, unsigned b1) {
    asm volatile(
        "mma.sync.aligned.m16n8k8.row.col.f32.tf32.tf32.f32 "
        "{%0,%1,%2,%3}, {%4,%5,%6,%7}, {%8,%9}, {%0,%1,%2,%3};"
        : "+f"(c[0]), "+f"(c[1]), "+f"(c[2]), "+f"(c[3])
        : "r"(a0), "r"(a1), "r"(a2), "r"(a3), "r"(b0), "r"(b1));
}

__global__ __launch_bounds__(NTHREADS, 1)
void edgenet_kernel(const float* __restrict__ nodef,
                    const int* __restrict__ eidx,          // int32 (jax x64 disabled)
                    const float* __restrict__ eattr,
                    const float* __restrict__ W1, const float* __restrict__ b1,
                    const float* __restrict__ g1, const float* __restrict__ be1,
                    const float* __restrict__ W2, const float* __restrict__ b2,
                    const float* __restrict__ g2, const float* __restrict__ be2,
                    const float* __restrict__ W3, const float* __restrict__ b3,
                    float* __restrict__ out, int E)
{
    extern __shared__ float sm[];
    const int tid = threadIdx.x;

    // ---- stage weights (once per persistent CTA) ----
    for (int i = tid; i < IN_DIM * HID; i += NTHREADS) {
        int k = i >> 6, n = i & 63;                 // W1 is [144][64] row-major
        sm[oW1 + n * AS + k] = tf32r(W1[i]);
    }
    for (int i = tid; i < HID * HID; i += NTHREADS) {
        int k = i >> 6, n = i & 63;
        sm[oW2 + n * HS + k] = tf32r(W2[i]);
    }
    if (tid < 64) {
        sm[oP + tid]        = b1[tid];
        sm[oP + 64  + tid]  = g1[tid];
        sm[oP + 128 + tid]  = be1[tid];
        sm[oP + 192 + tid]  = b2[tid];
        sm[oP + 256 + tid]  = g2[tid];
        sm[oP + 320 + tid]  = be2[tid];
        sm[oP + 384 + tid]  = W3[tid];
    }
    if (tid == 0) sm[oP + 448] = b3[0];

    const int warp = tid >> 5, lane = tid & 31;
    const int g = lane >> 2, tg = lane & 3;       // groupID / threadID_in_group
    const int numTiles = (E + TILE_M - 1) / TILE_M;

    for (int tile = blockIdx.x; tile < numTiles; tile += gridDim.x) {
        // ---------------- gather: 2 threads per edge ----------------
        {
            const int el = tid >> 1, half = tid & 1;
            const int e = tile * TILE_M + el;
            float* arow = &sm[oA + el * AS];
            if (e < E) {
                const int nidx = eidx[(size_t)half * (size_t)E + (size_t)e];
                const float4* src4 = reinterpret_cast<const float4*>(nodef + (size_t)nidx * 64);
                float4* d4 = reinterpret_cast<float4*>(arow + half * 64);
                #pragma unroll
                for (int i = 0; i < 16; i++) {
                    float4 v = src4[i];
                    v.x = tf32r(v.x); v.y = tf32r(v.y); v.z = tf32r(v.z); v.w = tf32r(v.w);
                    d4[i] = v;
                }
                const float4* ea4 = reinterpret_cast<const float4*>(eattr + (size_t)e * 16 + half * 8);
                float4* a4 = reinterpret_cast<float4*>(arow + 128 + half * 8);
                #pragma unroll
                for (int i = 0; i < 2; i++) {
                    float4 v = ea4[i];
                    v.x = tf32r(v.x); v.y = tf32r(v.y); v.z = tf32r(v.z); v.w = tf32r(v.w);
                    a4[i] = v;
                }
            } else {
                float4 z = make_float4(0.f, 0.f, 0.f, 0.f);
                float4* d4 = reinterpret_cast<float4*>(arow + half * 64);
                #pragma unroll
                for (int i = 0; i < 16; i++) d4[i] = z;
                float4* a4 = reinterpret_cast<float4*>(arow + 128 + half * 8);
                a4[0] = z; a4[1] = z;
            }
        }
        __syncthreads();

        float acc[8][4];

        // ---------------- GEMM1: rows [warp*16, warp*16+16), N=64, K=144 ----------------
        #pragma unroll
        for (int i = 0; i < 8; i++) { acc[i][0] = acc[i][1] = acc[i][2] = acc[i][3] = 0.f; }
        {
            const float* Ab = &sm[oA  + (warp * 16 + g) * AS + tg];
            const float* Bb = &sm[oW1 + g * AS + tg];
            #pragma unroll
            for (int ks = 0; ks < IN_DIM / 8; ks++) {
                const int k0 = ks * 8;
                unsigned a0 = __float_as_uint(Ab[k0]);
                unsigned a1 = __float_as_uint(Ab[8 * AS + k0]);
                unsigned a2 = __float_as_uint(Ab[k0 + 4]);
                unsigned a3 = __float_as_uint(Ab[8 * AS + k0 + 4]);
                #pragma unroll
                for (int nfr = 0; nfr < 8; nfr++) {
                    unsigned bb0 = __float_as_uint(Bb[nfr * 8 * AS + k0]);
                    unsigned bb1 = __float_as_uint(Bb[nfr * 8 * AS + k0 + 4]);
                    mma_tf32(acc[nfr], a0, a1, a2, a3, bb0, bb1);
                }
            }
        }

        // ---------------- bias + LN1 + LeakyReLU -> H (tf32) ----------------
        {
            float s0 = 0.f, q0 = 0.f, s1 = 0.f, q1 = 0.f;
            #pragma unroll
            for (int nfr = 0; nfr < 8; nfr++) {
                const int col = nfr * 8 + tg * 2;
                const float bc0 = sm[oP + col], bc1 = sm[oP + col + 1];
                acc[nfr][0] += bc0; acc[nfr][1] += bc1;
                acc[nfr][2] += bc0; acc[nfr][3] += bc1;
                s0 += acc[nfr][0] + acc[nfr][1];
                q0 += acc[nfr][0] * acc[nfr][0] + acc[nfr][1] * acc[nfr][1];
                s1 += acc[nfr][2] + acc[nfr][3];
                q1 += acc[nfr][2] * acc[nfr][2] + acc[nfr][3] * acc[nfr][3];
            }
            s0 += __shfl_xor_sync(0xffffffffu, s0, 1); s0 += __shfl_xor_sync(0xffffffffu, s0, 2);
            q0 += __shfl_xor_sync(0xffffffffu, q0, 1); q0 += __shfl_xor_sync(0xffffffffu, q0, 2);
            s1 += __shfl_xor_sync(0xffffffffu, s1, 1); s1 += __shfl_xor_sync(0xffffffffu, s1, 2);
            q1 += __shfl_xor_sync(0xffffffffu, q1, 1); q1 += __shfl_xor_sync(0xffffffffu, q1, 2);
            const float mu0 = s0 * (1.f / HID), mu1 = s1 * (1.f / HID);
            const float is0 = rsqrtf(fmaxf(q0 * (1.f / HID) - mu0 * mu0, 0.f) + 1e-5f);
            const float is1 = rsqrtf(fmaxf(q1 * (1.f / HID) - mu1 * mu1, 0.f) + 1e-5f);
            float* h0p = &sm[oH + (warp * 16 + g) * HS];
            float* h1p = &sm[oH + (warp * 16 + g + 8) * HS];
            #pragma unroll
            for (int nfr = 0; nfr < 8; nfr++) {
                const int col = nfr * 8 + tg * 2;
                const float ga0 = sm[oP + 64 + col],  ga1 = sm[oP + 64 + col + 1];
                const float bb0 = sm[oP + 128 + col], bb1 = sm[oP + 128 + col + 1];
                float h00 = (acc[nfr][0] - mu0) * is0 * ga0 + bb0;
                float h01 = (acc[nfr][1] - mu0) * is0 * ga1 + bb1;
                float h10 = (acc[nfr][2] - mu1) * is1 * ga0 + bb0;
                float h11 = (acc[nfr][3] - mu1) * is1 * ga1 + bb1;
                h00 = h00 < 0.f ? 0.1f * h00 : h00;
                h01 = h01 < 0.f ? 0.1f * h01 : h01;
                h10 = h10 < 0.f ? 0.1f * h10 : h10;
                h11 = h11 < 0.f ? 0.1f * h11 : h11;
                *reinterpret_cast<float2*>(h0p + col) = make_float2(tf32r(h00), tf32r(h01));
                *reinterpret_cast<float2*>(h1p + col) = make_float2(tf32r(h10), tf32r(h11));
            }
        }
        __syncthreads();

        // ---------------- GEMM2: K=64 ----------------
        #pragma unroll
        for (int i = 0; i < 8; i++) { acc[i][0] = acc[i][1] = acc[i][2] = acc[i][3] = 0.f; }
        {
            const float* Ab = &sm[oH  + (warp * 16 + g) * HS + tg];
            const float* Bb = &sm[oW2 + g * HS + tg];
            #pragma unroll
            for (int ks = 0; ks < HID / 8; ks++) {
                const int k0 = ks * 8;
                unsigned a0 = __float_as_uint(Ab[k0]);
                unsigned a1 = __float_as_uint(Ab[8 * HS + k0]);
                unsigned a2 = __float_as_uint(Ab[k0 + 4]);
                unsigned a3 = __float_as_uint(Ab[8 * HS + k0 + 4]);
                #pragma unroll
                for (int nfr = 0; nfr < 8; nfr++) {
                    unsigned bb0 = __float_as_uint(Bb[nfr * 8 * HS + k0]);
                    unsigned bb1 = __float_as_uint(Bb[nfr * 8 * HS + k0 + 4]);
                    mma_tf32(acc[nfr], a0, a1, a2, a3, bb0, bb1);
                }
            }
        }

        // ---------------- bias + LN2 + LeakyReLU + layer3 dot -> out ----------------
        {
            float s0 = 0.f, q0 = 0.f, s1 = 0.f, q1 = 0.f;
            #pragma unroll
            for (int nfr = 0; nfr < 8; nfr++) {
                const int col = nfr * 8 + tg * 2;
                const float bc0 = sm[oP + 192 + col], bc1 = sm[oP + 192 + col + 1];
                acc[nfr][0] += bc0; acc[nfr][1] += bc1;
                acc[nfr][2] += bc0; acc[nfr][3] += bc1;
                s0 += acc[nfr][0] + acc[nfr][1];
                q0 += acc[nfr][0] * acc[nfr][0] + acc[nfr][1] * acc[nfr][1];
                s1 += acc[nfr][2] + acc[nfr][3];
                q1 += acc[nfr][2] * acc[nfr][2] + acc[nfr][3] * acc[nfr][3];
            }
            s0 += __shfl_xor_sync(0xffffffffu, s0, 1); s0 += __shfl_xor_sync(0xffffffffu, s0, 2);
            q0 += __shfl_xor_sync(0xffffffffu, q0, 1); q0 += __shfl_xor_sync(0xffffffffu, q0, 2);
            s1 += __shfl_xor_sync(0xffffffffu, s1, 1); s1 += __shfl_xor_sync(0xffffffffu, s1, 2);
            q1 += __shfl_xor_sync(0xffffffffu, q1, 1); q1 += __shfl_xor_sync(0xffffffffu, q1, 2);
            const float mu0 = s0 * (1.f / HID), mu1 = s1 * (1.f / HID);
            const float is0 = rsqrtf(fmaxf(q0 * (1.f / HID) - mu0 * mu0, 0.f) + 1e-5f);
            const float is1 = rsqrtf(fmaxf(q1 * (1.f / HID) - mu1 * mu1, 0.f) + 1e-5f);
            float y0 = 0.f, y1v = 0.f;
            #pragma unroll
            for (int nfr = 0; nfr < 8; nfr++) {
                const int col = nfr * 8 + tg * 2;
                const float ga0 = sm[oP + 256 + col], ga1 = sm[oP + 256 + col + 1];
                const float bb0 = sm[oP + 320 + col], bb1 = sm[oP + 320 + col + 1];
                float h00 = (acc[nfr][0] - mu0) * is0 * ga0 + bb0;
                float h01 = (acc[nfr][1] - mu0) * is0 * ga1 + bb1;
                float h10 = (acc[nfr][2] - mu1) * is1 * ga0 + bb0;
                float h11 = (acc[nfr][3] - mu1) * is1 * ga1 + bb1;
                h00 = h00 < 0.f ? 0.1f * h00 : h00;
                h01 = h01 < 0.f ? 0.1f * h01 : h01;
                h10 = h10 < 0.f ? 0.1f * h10 : h10;
                h11 = h11 < 0.f ? 0.1f * h11 : h11;
                const float w30 = sm[oP + 384 + col], w31 = sm[oP + 384 + col + 1];
                y0  += h00 * w30 + h01 * w31;
                y1v += h10 * w30 + h11 * w31;
            }
            y0  += __shfl_xor_sync(0xffffffffu, y0, 1);  y0  += __shfl_xor_sync(0xffffffffu, y0, 2);
            y1v += __shfl_xor_sync(0xffffffffu, y1v, 1); y1v += __shfl_xor_sync(0xffffffffu, y1v, 2);
            if (tg == 0) {
                const float b3s = sm[oP + 448];
                const int r = tile * TILE_M + warp * 16 + g;
                if (r < E)     out[r]     = y0  + b3s;
                if (r + 8 < E) out[r + 8] = y1v + b3s;
            }
        }
    }
}

extern "C" void kernel_launch(void* const* d_in, const int* in_sizes, int n_in,
                              void* d_out, int out_size) {
    const float* nodef = (const float*)d_in[0];
    const int*   eidx  = (const int*)d_in[1];     // int32: jax x64 is disabled by default
    const float* eattr = (const float*)d_in[2];
    const float* W1 = (const float*)d_in[3];
    const float* b1 = (const float*)d_in[4];
    const float* g1 = (const float*)d_in[5];
    const float* be1 = (const float*)d_in[6];
    const float* W2 = (const float*)d_in[7];
    const float* b2 = (const float*)d_in[8];
    const float* g2 = (const float*)d_in[9];
    const float* be2 = (const float*)d_in[10];
    const float* W3 = (const float*)d_in[11];
    const float* b3 = (const float*)d_in[12];
    float* out = (float*)d_out;

    const int E = out_size;          // output is (E,) — robust to index dtype width
    if (E <= 0) return;

    cudaFuncSetAttribute(edgenet_kernel, cudaFuncAttributeMaxDynamicSharedMemorySize, SMEM_BYTES);

    int dev = 0;
    cudaGetDevice(&dev);
    int sms = 148;
    cudaDeviceGetAttribute(&sms, cudaDevAttrMultiProcessorCount, dev);

    const int numTiles = (E + TILE_M - 1) / TILE_M;
    const int grid = (numTiles < sms) ? numTiles : sms;

    edgenet_kernel<<<grid, NTHREADS, SMEM_BYTES>>>(
        nodef, eidx, eattr, W1, b1, g1, be1, W2, b2, g2, be2, W3, b3, out, E);
}

// round 3
// speedup vs baseline: 1.2546x; 1.2546x over previous
#include <cuda_runtime.h>
#include <cstdint>
#include <cstddef>

#define HID      64
#define IN_DIM   144
#define NTHREADS 256

#define AS   148   // A-tile row stride (floats): 148 ≡ 20 (mod 32) -> conflict-free scalar frag loads
#define HS   68    // H row stride: 68 ≡ 4 (mod 32) -> conflict-free
#define WS1  144   // W1T row stride: ≡ 16 (mod 32) -> conflict-free LDS.128
#define WS2  80    // W2T row stride: ≡ 16 (mod 32) -> conflict-free LDS.128

// SMEM layout (float offsets)
#define oW1 0                       // W1 permuted  [64][WS1]
#define oW2 (oW1 + 64*WS1)          // W2 permuted  [64][WS2]
#define oA  (oW2 + 64*WS2)          // per-warp A slices: 8 x 32 x AS   (H aliased on top)
#define oP  (oA + 256*AS)           // b1,g1,be1,b2,g2,be2,W3 (7x64) + b3
#define SMEM_FLOATS (oP + 452)
#define SMEM_BYTES  (SMEM_FLOATS * 4)   // 210,704 B

__device__ __forceinline__ float tf32r(float x) {
    unsigned u;
    asm("cvt.rna.tf32.f32 %0, %1;" : "=r"(u) : "f"(x));
    return __uint_as_float(u);
}

__device__ __forceinline__ void mma_tf32(float* c,
                                         unsigned a0, unsigned a1, unsigned a2, unsigned a3,
                                         unsigned b0, unsigned b1) {
    asm volatile(
        "mma.sync.aligned.m16n8k8.row.col.f32.tf32.tf32.f32 "
        "{%0,%1,%2,%3}, {%4,%5,%6,%7}, {%8,%9}, {%0,%1,%2,%3};"
        : "+f"(c[0]), "+f"(c[1]), "+f"(c[2]), "+f"(c[3])
        : "r"(a0), "r"(a1), "r"(a2), "r"(a3), "r"(b0), "r"(b1));
}

__global__ __launch_bounds__(NTHREADS, 1)
void edgenet_kernel(const float* __restrict__ nodef,
                    const int* __restrict__ eidx,
                    const float* __restrict__ eattr,
                    const float* __restrict__ W1, const float* __restrict__ b1,
                    const float* __restrict__ g1, const float* __restrict__ be1,
                    const float* __restrict__ W2, const float* __restrict__ b2,
                    const float* __restrict__ g2, const float* __restrict__ be2,
                    const float* __restrict__ W3, const float* __restrict__ b3,
                    float* __restrict__ out, int E)
{
    extern __shared__ float sm[];
    const int tid = threadIdx.x;

    // ---- stage weights, permuted k-layout: within each 16-k chunk,
    // position p = tg*4 + j holds original k = chunk*16 + j*4 + tg,
    // so a thread's 4 B-regs (2 k-steps) are one 16B load. ----
    for (int i = tid; i < 64 * 144; i += NTHREADS) {
        const int n = i / 144, p = i % 144;
        const int c = p >> 4, q = p & 15, tg_s = q >> 2, j = q & 3;
        const int k = c * 16 + j * 4 + tg_s;
        sm[oW1 + n * WS1 + p] = tf32r(W1[k * 64 + n]);
    }
    for (int i = tid; i < 64 * 64; i += NTHREADS) {
        const int n = i >> 6, p = i & 63;
        const int c = p >> 4, q = p & 15, tg_s = q >> 2, j = q & 3;
        const int k = c * 16 + j * 4 + tg_s;
        sm[oW2 + n * WS2 + p] = tf32r(W2[k * 64 + n]);
    }
    if (tid < 64) {
        sm[oP + tid]        = b1[tid];
        sm[oP + 64  + tid]  = g1[tid];
        sm[oP + 128 + tid]  = be1[tid];
        sm[oP + 192 + tid]  = b2[tid];
        sm[oP + 256 + tid]  = g2[tid];
        sm[oP + 320 + tid]  = be2[tid];
        sm[oP + 384 + tid]  = W3[tid];
    }
    if (tid == 0) sm[oP + 448] = b3[0];
    __syncthreads();

    const int warp = tid >> 5, lane = tid & 31;
    const int g = lane >> 2, tg = lane & 3;
    float* const Aw = &sm[oA + warp * 32 * AS];   // this warp's private 32-row slice
    float* const Hw = Aw;                          // H aliases A (A dead after GEMM1)

    const int nChunks = (E + 31) / 32;

    for (int ch = blockIdx.x * 8 + warp; ch < nChunks; ch += gridDim.x * 8) {
        __syncwarp();   // prior iteration's H reads done before overwriting the slice

        // ---------------- gather: 1 thread = 1 edge (warp-local rows) ----------------
        {
            const int e = ch * 32 + lane;
            float* arow = Aw + lane * AS;
            if (e < E) {
                const int si = eidx[e];
                const int di = eidx[(size_t)E + e];
                const float4* s4 = reinterpret_cast<const float4*>(nodef + (size_t)si * 64);
                const float4* d4 = reinterpret_cast<const float4*>(nodef + (size_t)di * 64);
                float4* a4 = reinterpret_cast<float4*>(arow);
                #pragma unroll
                for (int i = 0; i < 16; i++) {
                    float4 v = s4[i];
                    v.x = tf32r(v.x); v.y = tf32r(v.y); v.z = tf32r(v.z); v.w = tf32r(v.w);
                    a4[i] = v;
                }
                #pragma unroll
                for (int i = 0; i < 16; i++) {
                    float4 v = d4[i];
                    v.x = tf32r(v.x); v.y = tf32r(v.y); v.z = tf32r(v.z); v.w = tf32r(v.w);
                    a4[16 + i] = v;
                }
                const float4* e4 = reinterpret_cast<const float4*>(eattr + (size_t)e * 16);
                #pragma unroll
                for (int i = 0; i < 4; i++) {
                    float4 v = e4[i];
                    v.x = tf32r(v.x); v.y = tf32r(v.y); v.z = tf32r(v.z); v.w = tf32r(v.w);
                    a4[32 + i] = v;
                }
            } else {
                float4 z = make_float4(0.f, 0.f, 0.f, 0.f);
                float4* a4 = reinterpret_cast<float4*>(arow);
                #pragma unroll
                for (int i = 0; i < 36; i++) a4[i] = z;
            }
        }
        __syncwarp();

        float acc[2][8][4];
        #pragma unroll
        for (int mt = 0; mt < 2; mt++)
            #pragma unroll
            for (int nf = 0; nf < 8; nf++)
                acc[mt][nf][0] = acc[mt][nf][1] = acc[mt][nf][2] = acc[mt][nf][3] = 0.f;

        // ---------------- GEMM1: 32 rows x 64 x K=144 ----------------
        {
            const float* Bw = &sm[oW1 + g * WS1 + tg * 4];
            #pragma unroll
            for (int c = 0; c < 9; c++) {
                const int kc = c * 16;
                float4 bv[8];
                #pragma unroll
                for (int nf = 0; nf < 8; nf++)
                    bv[nf] = *reinterpret_cast<const float4*>(Bw + nf * 8 * WS1 + kc);
                #pragma unroll
                for (int s = 0; s < 2; s++) {
                    const int k = kc + s * 8 + tg;
                    unsigned a00 = __float_as_uint(Aw[g * AS + k]);
                    unsigned a01 = __float_as_uint(Aw[(g + 8) * AS + k]);
                    unsigned a02 = __float_as_uint(Aw[g * AS + k + 4]);
                    unsigned a03 = __float_as_uint(Aw[(g + 8) * AS + k + 4]);
                    unsigned a10 = __float_as_uint(Aw[(g + 16) * AS + k]);
                    unsigned a11 = __float_as_uint(Aw[(g + 24) * AS + k]);
                    unsigned a12 = __float_as_uint(Aw[(g + 16) * AS + k + 4]);
                    unsigned a13 = __float_as_uint(Aw[(g + 24) * AS + k + 4]);
                    #pragma unroll
                    for (int nf = 0; nf < 8; nf++) {
                        const unsigned bb0 = s ? __float_as_uint(bv[nf].z) : __float_as_uint(bv[nf].x);
                        const unsigned bb1 = s ? __float_as_uint(bv[nf].w) : __float_as_uint(bv[nf].y);
                        mma_tf32(acc[0][nf], a00, a01, a02, a03, bb0, bb1);
                        mma_tf32(acc[1][nf], a10, a11, a12, a13, bb0, bb1);
                    }
                }
            }
        }

        // ---------------- bias + LN1 + LeakyReLU -> H (tf32) ----------------
        {
            float s[4] = {0.f, 0.f, 0.f, 0.f}, q[4] = {0.f, 0.f, 0.f, 0.f};
            #pragma unroll
            for (int mt = 0; mt < 2; mt++)
                #pragma unroll
                for (int nf = 0; nf < 8; nf++) {
                    const int col = nf * 8 + tg * 2;
                    const float bc0 = sm[oP + col], bc1 = sm[oP + col + 1];
                    float* a = acc[mt][nf];
                    a[0] += bc0; a[1] += bc1; a[2] += bc0; a[3] += bc1;
                    s[mt * 2]     += a[0] + a[1];
                    q[mt * 2]     += a[0] * a[0] + a[1] * a[1];
                    s[mt * 2 + 1] += a[2] + a[3];
                    q[mt * 2 + 1] += a[2] * a[2] + a[3] * a[3];
                }
            float mu[4], is[4];
            #pragma unroll
            for (int r = 0; r < 4; r++) {
                s[r] += __shfl_xor_sync(0xffffffffu, s[r], 1);
                s[r] += __shfl_xor_sync(0xffffffffu, s[r], 2);
                q[r] += __shfl_xor_sync(0xffffffffu, q[r], 1);
                q[r] += __shfl_xor_sync(0xffffffffu, q[r], 2);
                mu[r] = s[r] * (1.f / HID);
                is[r] = rsqrtf(fmaxf(q[r] * (1.f / HID) - mu[r] * mu[r], 0.f) + 1e-5f);
            }
            #pragma unroll
            for (int mt = 0; mt < 2; mt++) {
                float* h0p = Hw + (g + mt * 16) * HS;
                float* h1p = Hw + (g + 8 + mt * 16) * HS;
                const float mu0 = mu[mt * 2], is0 = is[mt * 2];
                const float mu1 = mu[mt * 2 + 1], is1 = is[mt * 2 + 1];
                #pragma unroll
                for (int nf = 0; nf < 8; nf++) {
                    const int col = nf * 8 + tg * 2;
                    const float ga0 = sm[oP + 64 + col],  ga1 = sm[oP + 64 + col + 1];
                    const float bb0 = sm[oP + 128 + col], bb1 = sm[oP + 128 + col + 1];
                    const float* a = acc[mt][nf];
                    float h00 = (a[0] - mu0) * is0 * ga0 + bb0;
                    float h01 = (a[1] - mu0) * is0 * ga1 + bb1;
                    float h10 = (a[2] - mu1) * is1 * ga0 + bb0;
                    float h11 = (a[3] - mu1) * is1 * ga1 + bb1;
                    h00 = h00 < 0.f ? 0.1f * h00 : h00;
                    h01 = h01 < 0.f ? 0.1f * h01 : h01;
                    h10 = h10 < 0.f ? 0.1f * h10 : h10;
                    h11 = h11 < 0.f ? 0.1f * h11 : h11;
                    *reinterpret_cast<float2*>(h0p + col) = make_float2(tf32r(h00), tf32r(h01));
                    *reinterpret_cast<float2*>(h1p + col) = make_float2(tf32r(h10), tf32r(h11));
                }
            }
        }
        __syncwarp();

        // ---------------- GEMM2: 32 rows x 64 x K=64 ----------------
        #pragma unroll
        for (int mt = 0; mt < 2; mt++)
            #pragma unroll
            for (int nf = 0; nf < 8; nf++)
                acc[mt][nf][0] = acc[mt][nf][1] = acc[mt][nf][2] = acc[mt][nf][3] = 0.f;
        {
            const float* Bw = &sm[oW2 + g * WS2 + tg * 4];
            #pragma unroll
            for (int c = 0; c < 4; c++) {
                const int kc = c * 16;
                float4 bv[8];
                #pragma unroll
                for (int nf = 0; nf < 8; nf++)
                    bv[nf] = *reinterpret_cast<const float4*>(Bw + nf * 8 * WS2 + kc);
                #pragma unroll
                for (int s = 0; s < 2; s++) {
                    const int k = kc + s * 8 + tg;
                    unsigned a00 = __float_as_uint(Hw[g * HS + k]);
                    unsigned a01 = __float_as_uint(Hw[(g + 8) * HS + k]);
                    unsigned a02 = __float_as_uint(Hw[g * HS + k + 4]);
                    unsigned a03 = __float_as_uint(Hw[(g + 8) * HS + k + 4]);
                    unsigned a10 = __float_as_uint(Hw[(g + 16) * HS + k]);
                    unsigned a11 = __float_as_uint(Hw[(g + 24) * HS + k]);
                    unsigned a12 = __float_as_uint(Hw[(g + 16) * HS + k + 4]);
                    unsigned a13 = __float_as_uint(Hw[(g + 24) * HS + k + 4]);
                    #pragma unroll
                    for (int nf = 0; nf < 8; nf++) {
                        const unsigned bb0 = s ? __float_as_uint(bv[nf].z) : __float_as_uint(bv[nf].x);
                        const unsigned bb1 = s ? __float_as_uint(bv[nf].w) : __float_as_uint(bv[nf].y);
                        mma_tf32(acc[0][nf], a00, a01, a02, a03, bb0, bb1);
                        mma_tf32(acc[1][nf], a10, a11, a12, a13, bb0, bb1);
                    }
                }
            }
        }

        // ---------------- bias + LN2 + LeakyReLU + layer3 dot -> out ----------------
        {
            float s[4] = {0.f, 0.f, 0.f, 0.f}, q[4] = {0.f, 0.f, 0.f, 0.f};
            #pragma unroll
            for (int mt = 0; mt < 2; mt++)
                #pragma unroll
                for (int nf = 0; nf < 8; nf++) {
                    const int col = nf * 8 + tg * 2;
                    const float bc0 = sm[oP + 192 + col], bc1 = sm[oP + 192 + col + 1];
                    float* a = acc[mt][nf];
                    a[0] += bc0; a[1] += bc1; a[2] += bc0; a[3] += bc1;
                    s[mt * 2]     += a[0] + a[1];
                    q[mt * 2]     += a[0] * a[0] + a[1] * a[1];
                    s[mt * 2 + 1] += a[2] + a[3];
                    q[mt * 2 + 1] += a[2] * a[2] + a[3] * a[3];
                }
            float mu[4], is[4];
            #pragma unroll
            for (int r = 0; r < 4; r++) {
                s[r] += __shfl_xor_sync(0xffffffffu, s[r], 1);
                s[r] += __shfl_xor_sync(0xffffffffu, s[r], 2);
                q[r] += __shfl_xor_sync(0xffffffffu, q[r], 1);
                q[r] += __shfl_xor_sync(0xffffffffu, q[r], 2);
                mu[r] = s[r] * (1.f / HID);
                is[r] = rsqrtf(fmaxf(q[r] * (1.f / HID) - mu[r] * mu[r], 0.f) + 1e-5f);
            }
            float y[4] = {0.f, 0.f, 0.f, 0.f};
            #pragma unroll
            for (int mt = 0; mt < 2; mt++)
                #pragma unroll
                for (int nf = 0; nf < 8; nf++) {
                    const int col = nf * 8 + tg * 2;
                    const float ga0 = sm[oP + 256 + col], ga1 = sm[oP + 256 + col + 1];
                    const float bb0 = sm[oP + 320 + col], bb1 = sm[oP + 320 + col + 1];
                    const float w30 = sm[oP + 384 + col], w31 = sm[oP + 384 + col + 1];
                    const float* a = acc[mt][nf];
                    float h00 = (a[0] - mu[mt * 2]) * is[mt * 2] * ga0 + bb0;
                    float h01 = (a[1] - mu[mt * 2]) * is[mt * 2] * ga1 + bb1;
                    float h10 = (a[2] - mu[mt * 2 + 1]) * is[mt * 2 + 1] * ga0 + bb0;
                    float h11 = (a[3] - mu[mt * 2 + 1]) * is[mt * 2 + 1] * ga1 + bb1;
                    h00 = h00 < 0.f ? 0.1f * h00 : h00;
                    h01 = h01 < 0.f ? 0.1f * h01 : h01;
                    h10 = h10 < 0.f ? 0.1f * h10 : h10;
                    h11 = h11 < 0.f ? 0.1f * h11 : h11;
                    y[mt * 2]     += h00 * w30 + h01 * w31;
                    y[mt * 2 + 1] += h10 * w30 + h11 * w31;
                }
            #pragma unroll
            for (int r = 0; r < 4; r++) {
                y[r] += __shfl_xor_sync(0xffffffffu, y[r], 1);
                y[r] += __shfl_xor_sync(0xffffffffu, y[r], 2);
            }
            if (tg == 0) {
                const float b3s = sm[oP + 448];
                const int base = ch * 32;
                #pragma unroll
                for (int r = 0; r < 4; r++) {
                    const int e = base + g + ((r & 1) ? 8 : 0) + ((r >> 1) ? 16 : 0);
                    if (e < E) out[e] = y[r] + b3s;
                }
            }
        }
    }
}

extern "C" void kernel_launch(void* const* d_in, const int* in_sizes, int n_in,
                              void* d_out, int out_size) {
    const float* nodef = (const float*)d_in[0];
    const int*   eidx  = (const int*)d_in[1];
    const float* eattr = (const float*)d_in[2];
    const float* W1 = (const float*)d_in[3];
    const float* b1 = (const float*)d_in[4];
    const float* g1 = (const float*)d_in[5];
    const float* be1 = (const float*)d_in[6];
    const float* W2 = (const float*)d_in[7];
    const float* b2 = (const float*)d_in[8];
    const float* g2 = (const float*)d_in[9];
    const float* be2 = (const float*)d_in[10];
    const float* W3 = (const float*)d_in[11];
    const float* b3 = (const float*)d_in[12];
    float* out = (float*)d_out;

    const int E = out_size;
    if (E <= 0) return;

    cudaFuncSetAttribute(edgenet_kernel, cudaFuncAttributeMaxDynamicSharedMemorySize, SMEM_BYTES);

    int dev = 0;
    cudaGetDevice(&dev);
    int sms = 148;
    cudaDeviceGetAttribute(&sms, cudaDevAttrMultiProcessorCount, dev);

    const int nChunks = (E + 31) / 32;
    const int ctasNeeded = (nChunks + 7) / 8;
    const int grid = (ctasNeeded < sms) ? ctasNeeded : sms;

    edgenet_kernel<<<grid, NTHREADS, SMEM_BYTES>>>(
        nodef, eidx, eattr, W1, b1, g1, be1, W2, b2, g2, be2, W3, b3, out, E);
}

// round 5
// speedup vs baseline: 1.4221x; 1.1335x over previous
#include <cuda_runtime.h>
#include <cstdint>
#include <cstddef>

#define HID      64
#define NTHREADS 384
#define NW       12     // warps per CTA

#define ASL  84    // A/H slice row stride (floats): 84 ≡ 20 (mod 32) -> conflict-free scalar LDS
#define WS1  144   // W1T row stride: ≡ 16 (mod 32) -> conflict-free LDS.128 (per-8-lane phases)
#define WS2  80    // W2T row stride: ≡ 16 (mod 32) -> conflict-free LDS.128

// SMEM layout (float offsets)
#define oW1 0                        // W1 permuted  [64][WS1]
#define oW2 (oW1 + 64*WS1)           // W2 permuted  [64][WS2]
#define oA  (oW2 + 64*WS2)           // per-warp slices: NW x 32 x ASL  (src->dst+eattr->H reuse)
#define oP  (oA + NW*32*ASL)         // b1,g1,be1,b2,g2,be2,W3 (7x64) + b3
#define SMEM_FLOATS (oP + 452)
#define SMEM_BYTES  (SMEM_FLOATS * 4)   // 188,176 B

__device__ __forceinline__ float tf32r(float x) {
    unsigned u;
    asm("cvt.rna.tf32.f32 %0, %1;" : "=r"(u) : "f"(x));
    return __uint_as_float(u);
}

__device__ __forceinline__ void mma_tf32(float* c,
                                         unsigned a0, unsigned a1, unsigned a2, unsigned a3,
                                         unsigned b0, unsigned b1) {
    asm volatile(
        "mma.sync.aligned.m16n8k8.row.col.f32.tf32.tf32.f32 "
        "{%0,%1,%2,%3}, {%4,%5,%6,%7}, {%8,%9}, {%0,%1,%2,%3};"
        : "+f"(c[0]), "+f"(c[1]), "+f"(c[2]), "+f"(c[3])
        : "r"(a0), "r"(a1), "r"(a2), "r"(a3), "r"(b0), "r"(b1));
}

// one K-chunk-range of GEMM accumulation: buffer chunks [0, nc), weight chunks [wc0, wc0+nc)
__device__ __forceinline__ void gemm_phase(float acc[2][8][4],
                                           const float* __restrict__ Aw,
                                           const float* __restrict__ Bw,
                                           int nc, int wc0, int ws, int as,
                                           int g, int tg) {
    for (int c = 0; c < nc; c++) {
        const int kc = c * 16;
        const int kw = (wc0 + c) * 16;
        float4 bv[8];
        #pragma unroll
        for (int nf = 0; nf < 8; nf++)
            bv[nf] = *reinterpret_cast<const float4*>(Bw + nf * 8 * ws + kw);
        #pragma unroll
        for (int s = 0; s < 2; s++) {
            const int k = kc + s * 8 + tg;
            unsigned a00 = __float_as_uint(Aw[g * as + k]);
            unsigned a01 = __float_as_uint(Aw[(g + 8) * as + k]);
            unsigned a02 = __float_as_uint(Aw[g * as + k + 4]);
            unsigned a03 = __float_as_uint(Aw[(g + 8) * as + k + 4]);
            unsigned a10 = __float_as_uint(Aw[(g + 16) * as + k]);
            unsigned a11 = __float_as_uint(Aw[(g + 24) * as + k]);
            unsigned a12 = __float_as_uint(Aw[(g + 16) * as + k + 4]);
            unsigned a13 = __float_as_uint(Aw[(g + 24) * as + k + 4]);
            #pragma unroll
            for (int nf = 0; nf < 8; nf++) {
                const unsigned bb0 = s ? __float_as_uint(bv[nf].z) : __float_as_uint(bv[nf].x);
                const unsigned bb1 = s ? __float_as_uint(bv[nf].w) : __float_as_uint(bv[nf].y);
                mma_tf32(acc[0][nf], a00, a01, a02, a03, bb0, bb1);
                mma_tf32(acc[1][nf], a10, a11, a12, a13, bb0, bb1);
            }
        }
    }
}

__global__ __launch_bounds__(NTHREADS, 1)
void edgenet_kernel(const float* __restrict__ nodef,
                    const int* __restrict__ eidx,
                    const float* __restrict__ eattr,
                    const float* __restrict__ W1, const float* __restrict__ b1,
                    const float* __restrict__ g1, const float* __restrict__ be1,
                    const float* __restrict__ W2, const float* __restrict__ b2,
                    const float* __restrict__ g2, const float* __restrict__ be2,
                    const float* __restrict__ W3, const float* __restrict__ b3,
                    float* __restrict__ out, int E)
{
    extern __shared__ float sm[];
    const int tid = threadIdx.x;

    // ---- stage weights, permuted k-layout: within each 16-k chunk,
    // position p = tg*4 + j holds original k = chunk*16 + j*4 + tg ----
    for (int i = tid; i < 64 * 144; i += NTHREADS) {
        const int n = i / 144, p = i % 144;
        const int c = p >> 4, q = p & 15, tg_s = q >> 2, j = q & 3;
        const int k = c * 16 + j * 4 + tg_s;
        sm[oW1 + n * WS1 + p] = tf32r(W1[k * 64 + n]);
    }
    for (int i = tid; i < 64 * 64; i += NTHREADS) {
        const int n = i >> 6, p = i & 63;
        const int c = p >> 4, q = p & 15, tg_s = q >> 2, j = q & 3;
        const int k = c * 16 + j * 4 + tg_s;
        sm[oW2 + n * WS2 + p] = tf32r(W2[k * 64 + n]);
    }
    if (tid < 64) {
        sm[oP + tid]        = b1[tid];
        sm[oP + 64  + tid]  = g1[tid];
        sm[oP + 128 + tid]  = be1[tid];
        sm[oP + 192 + tid]  = b2[tid];
        sm[oP + 256 + tid]  = g2[tid];
        sm[oP + 320 + tid]  = be2[tid];
        sm[oP + 384 + tid]  = W3[tid];
    }
    if (tid == 0) sm[oP + 448] = b3[0];
    __syncthreads();

    const int warp = tid >> 5, lane = tid & 31;
    const int g = lane >> 2, tg = lane & 3;
    float* const Aw = &sm[oA + warp * 32 * ASL];   // warp-private 32-row slice

    const int nChunks = (E + 31) / 32;

    for (int ch = blockIdx.x * NW + warp; ch < nChunks; ch += gridDim.x * NW) {
        const int e = ch * 32 + lane;
        float* arow = Aw + lane * ASL;

        __syncwarp();   // prior iteration's H reads done before overwrite

        // ---------------- phase A: gather src features (k 0..63) ----------------
        if (e < E) {
            const int si = eidx[e];
            const float4* s4 = reinterpret_cast<const float4*>(nodef + (size_t)si * 64);
            float4* a4 = reinterpret_cast<float4*>(arow);
            #pragma unroll
            for (int i = 0; i < 16; i++) {
                float4 v = s4[i];
                v.x = tf32r(v.x); v.y = tf32r(v.y); v.z = tf32r(v.z); v.w = tf32r(v.w);
                a4[i] = v;
            }
        } else {
            const float4 z = make_float4(0.f, 0.f, 0.f, 0.f);
            float4* a4 = reinterpret_cast<float4*>(arow);
            #pragma unroll
            for (int i = 0; i < 16; i++) a4[i] = z;
        }
        __syncwarp();

        float acc[2][8][4];
        #pragma unroll
        for (int mt = 0; mt < 2; mt++)
            #pragma unroll
            for (int nf = 0; nf < 8; nf++)
                acc[mt][nf][0] = acc[mt][nf][1] = acc[mt][nf][2] = acc[mt][nf][3] = 0.f;

        // GEMM1 phase A: buffer chunks 0..3 <-> W1 chunks 0..3 (k 0..63)
        gemm_phase(acc, Aw, &sm[oW1 + g * WS1 + tg * 4], 4, 0, WS1, ASL, g, tg);
        __syncwarp();   // all lanes' phase-A reads done before overwrite

        // ---------------- phase B: gather dst (k->0..63) + eattr (k->64..79) ----------------
        if (e < E) {
            const int di = eidx[(size_t)E + e];
            const float4* d4 = reinterpret_cast<const float4*>(nodef + (size_t)di * 64);
            const float4* e4 = reinterpret_cast<const float4*>(eattr + (size_t)e * 16);
            float4* a4 = reinterpret_cast<float4*>(arow);
            #pragma unroll
            for (int i = 0; i < 16; i++) {
                float4 v = d4[i];
                v.x = tf32r(v.x); v.y = tf32r(v.y); v.z = tf32r(v.z); v.w = tf32r(v.w);
                a4[i] = v;
            }
            #pragma unroll
            for (int i = 0; i < 4; i++) {
                float4 v = e4[i];
                v.x = tf32r(v.x); v.y = tf32r(v.y); v.z = tf32r(v.z); v.w = tf32r(v.w);
                a4[16 + i] = v;
            }
        } else {
            const float4 z = make_float4(0.f, 0.f, 0.f, 0.f);
            float4* a4 = reinterpret_cast<float4*>(arow);
            #pragma unroll
            for (int i = 0; i < 20; i++) a4[i] = z;
        }
        __syncwarp();

        // GEMM1 phase B: buffer chunks 0..4 <-> W1 chunks 4..8 (k 64..143)
        gemm_phase(acc, Aw, &sm[oW1 + g * WS1 + tg * 4], 5, 4, WS1, ASL, g, tg);
        __syncwarp();   // all lanes' phase-B reads done before H overwrite

        // ---------------- bias + LN1 + LeakyReLU -> H (tf32, buffer k 0..63) ----------------
        {
            float s[4] = {0.f, 0.f, 0.f, 0.f}, q[4] = {0.f, 0.f, 0.f, 0.f};
            #pragma unroll
            for (int mt = 0; mt < 2; mt++)
                #pragma unroll
                for (int nf = 0; nf < 8; nf++) {
                    const int col = nf * 8 + tg * 2;
                    const float bc0 = sm[oP + col], bc1 = sm[oP + col + 1];
                    float* a = acc[mt][nf];
                    a[0] += bc0; a[1] += bc1; a[2] += bc0; a[3] += bc1;
                    s[mt * 2]     += a[0] + a[1];
                    q[mt * 2]     += a[0] * a[0] + a[1] * a[1];
                    s[mt * 2 + 1] += a[2] + a[3];
                    q[mt * 2 + 1] += a[2] * a[2] + a[3] * a[3];
                }
            float mu[4], is[4];
            #pragma unroll
            for (int r = 0; r < 4; r++) {
                s[r] += __shfl_xor_sync(0xffffffffu, s[r], 1);
                s[r] += __shfl_xor_sync(0xffffffffu, s[r], 2);
                q[r] += __shfl_xor_sync(0xffffffffu, q[r], 1);
                q[r] += __shfl_xor_sync(0xffffffffu, q[r], 2);
                mu[r] = s[r] * (1.f / HID);
                is[r] = rsqrtf(fmaxf(q[r] * (1.f / HID) - mu[r] * mu[r], 0.f) + 1e-5f);
            }
            #pragma unroll
            for (int mt = 0; mt < 2; mt++) {
                float* h0p = Aw + (g + mt * 16) * ASL;
                float* h1p = Aw + (g + 8 + mt * 16) * ASL;
                const float mu0 = mu[mt * 2], is0 = is[mt * 2];
                const float mu1 = mu[mt * 2 + 1], is1 = is[mt * 2 + 1];
                #pragma unroll
                for (int nf = 0; nf < 8; nf++) {
                    const int col = nf * 8 + tg * 2;
                    const float ga0 = sm[oP + 64 + col],  ga1 = sm[oP + 64 + col + 1];
                    const float bb0 = sm[oP + 128 + col], bb1 = sm[oP + 128 + col + 1];
                    const float* a = acc[mt][nf];
                    float h00 = (a[0] - mu0) * is0 * ga0 + bb0;
                    float h01 = (a[1] - mu0) * is0 * ga1 + bb1;
                    float h10 = (a[2] - mu1) * is1 * ga0 + bb0;
                    float h11 = (a[3] - mu1) * is1 * ga1 + bb1;
                    h00 = h00 < 0.f ? 0.1f * h00 : h00;
                    h01 = h01 < 0.f ? 0.1f * h01 : h01;
                    h10 = h10 < 0.f ? 0.1f * h10 : h10;
                    h11 = h11 < 0.f ? 0.1f * h11 : h11;
                    *reinterpret_cast<float2*>(h0p + col) = make_float2(tf32r(h00), tf32r(h01));
                    *reinterpret_cast<float2*>(h1p + col) = make_float2(tf32r(h10), tf32r(h11));
                }
            }
        }
        __syncwarp();

        // ---------------- GEMM2: 32 rows x 64 x K=64 ----------------
        #pragma unroll
        for (int mt = 0; mt < 2; mt++)
            #pragma unroll
            for (int nf = 0; nf < 8; nf++)
                acc[mt][nf][0] = acc[mt][nf][1] = acc[mt][nf][2] = acc[mt][nf][3] = 0.f;
        gemm_phase(acc, Aw, &sm[oW2 + g * WS2 + tg * 4], 4, 0, WS2, ASL, g, tg);

        // ---------------- bias + LN2 + LeakyReLU + layer3 dot -> out ----------------
        {
            float s[4] = {0.f, 0.f, 0.f, 0.f}, q[4] = {0.f, 0.f, 0.f, 0.f};
            #pragma unroll
            for (int mt = 0; mt < 2; mt++)
                #pragma unroll
                for (int nf = 0; nf < 8; nf++) {
                    const int col = nf * 8 + tg * 2;
                    const float bc0 = sm[oP + 192 + col], bc1 = sm[oP + 192 + col + 1];
                    float* a = acc[mt][nf];
                    a[0] += bc0; a[1] += bc1; a[2] += bc0; a[3] += bc1;
                    s[mt * 2]     += a[0] + a[1];
                    q[mt * 2]     += a[0] * a[0] + a[1] * a[1];
                    s[mt * 2 + 1] += a[2] + a[3];
                    q[mt * 2 + 1] += a[2] * a[2] + a[3] * a[3];
                }
            float mu[4], is[4];
            #pragma unroll
            for (int r = 0; r < 4; r++) {
                s[r] += __shfl_xor_sync(0xffffffffu, s[r], 1);
                s[r] += __shfl_xor_sync(0xffffffffu, s[r], 2);
                q[r] += __shfl_xor_sync(0xffffffffu, q[r], 1);
                q[r] += __shfl_xor_sync(0xffffffffu, q[r], 2);
                mu[r] = s[r] * (1.f / HID);
                is[r] = rsqrtf(fmaxf(q[r] * (1.f / HID) - mu[r] * mu[r], 0.f) + 1e-5f);
            }
            float y[4] = {0.f, 0.f, 0.f, 0.f};
            #pragma unroll
            for (int mt = 0; mt < 2; mt++)
                #pragma unroll
                for (int nf = 0; nf < 8; nf++) {
                    const int col = nf * 8 + tg * 2;
                    const float ga0 = sm[oP + 256 + col], ga1 = sm[oP + 256 + col + 1];
                    const float bb0 = sm[oP + 320 + col], bb1 = sm[oP + 320 + col + 1];
                    const float w30 = sm[oP + 384 + col], w31 = sm[oP + 384 + col + 1];
                    const float* a = acc[mt][nf];
                    float h00 = (a[0] - mu[mt * 2]) * is[mt * 2] * ga0 + bb0;
                    float h01 = (a[1] - mu[mt * 2]) * is[mt * 2] * ga1 + bb1;
                    float h10 = (a[2] - mu[mt * 2 + 1]) * is[mt * 2 + 1] * ga0 + bb0;
                    float h11 = (a[3] - mu[mt * 2 + 1]) * is[mt * 2 + 1] * ga1 + bb1;
                    h00 = h00 < 0.f ? 0.1f * h00 : h00;
                    h01 = h01 < 0.f ? 0.1f * h01 : h01;
                    h10 = h10 < 0.f ? 0.1f * h10 : h10;
                    h11 = h11 < 0.f ? 0.1f * h11 : h11;
                    y[mt * 2]     += h00 * w30 + h01 * w31;
                    y[mt * 2 + 1] += h10 * w30 + h11 * w31;
                }
            #pragma unroll
            for (int r = 0; r < 4; r++) {
                y[r] += __shfl_xor_sync(0xffffffffu, y[r], 1);
                y[r] += __shfl_xor_sync(0xffffffffu, y[r], 2);
            }
            if (tg == 0) {
                const float b3s = sm[oP + 448];
                const int base = ch * 32;
                #pragma unroll
                for (int r = 0; r < 4; r++) {
                    const int eo = base + g + ((r & 1) ? 8 : 0) + ((r >> 1) ? 16 : 0);
                    if (eo < E) out[eo] = y[r] + b3s;
                }
            }
        }
    }
}

extern "C" void kernel_launch(void* const* d_in, const int* in_sizes, int n_in,
                              void* d_out, int out_size) {
    const float* nodef = (const float*)d_in[0];
    const int*   eidx  = (const int*)d_in[1];
    const float* eattr = (const float*)d_in[2];
    const float* W1 = (const float*)d_in[3];
    const float* b1 = (const float*)d_in[4];
    const float* g1 = (const float*)d_in[5];
    const float* be1 = (const float*)d_in[6];
    const float* W2 = (const float*)d_in[7];
    const float* b2 = (const float*)d_in[8];
    const float* g2 = (const float*)d_in[9];
    const float* be2 = (const float*)d_in[10];
    const float* W3 = (const float*)d_in[11];
    const float* b3 = (const float*)d_in[12];
    float* out = (float*)d_out;

    const int E = out_size;
    if (E <= 0) return;

    cudaFuncSetAttribute(edgenet_kernel, cudaFuncAttributeMaxDynamicSharedMemorySize, SMEM_BYTES);

    int dev = 0;
    cudaGetDevice(&dev);
    int sms = 148;
    cudaDeviceGetAttribute(&sms, cudaDevAttrMultiProcessorCount, dev);

    const int nChunks = (E + 31) / 32;
    const int ctasNeeded = (nChunks + NW - 1) / NW;
    const int grid = (ctasNeeded < sms) ? ctasNeeded : sms;

    edgenet_kernel<<<grid, NTHREADS, SMEM_BYTES>>>(
        nodef, eidx, eattr, W1, b1, g1, be1, W2, b2, g2, be2, W3, b3, out, E);
}